// round 1
// baseline (speedup 1.0000x reference)
#include <cuda_runtime.h>

#define NV 5
#define NS 4
#define CC 32
#define HH 128
#define WW 160
#define DDEP 48
#define HWSZ (HH*WW)          // 20480
#define DHWSZ (DDEP*HWSZ)     // 983040

// ---------------- scratch (static device globals; no runtime allocation) ----
__device__ float g_rot[NS][9];
__device__ float g_trans[NS][3];
__device__ float g_feaT[NV*HWSZ*CC];            // (view, h, w, c)  13.1 MB
__device__ float g_var[(size_t)CC*DHWSZ];       // planar (c, d,h,w) 125.8 MB
__device__ float g_cost[DHWSZ];                 // (d,h,w) 3.9 MB

// ---------------- kernel 0: projection setup (1 thread) ---------------------
__global__ void k_setup(const float* __restrict__ pm) {
    if (threadIdx.x != 0 || blockIdx.x != 0) return;
    // pm: (B=1, N=5, 2, 4, 4)
    double fused[NV][16];
    for (int n = 0; n < NV; n++) {
        const float* p0 = pm + n * 32;       // (n,0,:,:)
        const float* p1 = p0 + 16;           // (n,1,:,:)
        for (int i = 0; i < 16; i++) fused[n][i] = (double)p0[i];
        for (int i = 0; i < 3; i++)
            for (int j = 0; j < 4; j++) {
                double s = 0.0;
                for (int k = 0; k < 3; k++) s += (double)p1[i*4+k] * (double)p0[k*4+j];
                fused[n][i*4+j] = s;
            }
    }
    // invert fused[0] via Gauss-Jordan with partial pivoting (double)
    double a[4][8];
    for (int i = 0; i < 4; i++)
        for (int j = 0; j < 4; j++) {
            a[i][j]   = fused[0][i*4+j];
            a[i][j+4] = (i == j) ? 1.0 : 0.0;
        }
    for (int col = 0; col < 4; col++) {
        int piv = col;
        for (int r = col + 1; r < 4; r++)
            if (fabs(a[r][col]) > fabs(a[piv][col])) piv = r;
        if (piv != col)
            for (int j = 0; j < 8; j++) { double t = a[col][j]; a[col][j] = a[piv][j]; a[piv][j] = t; }
        double d = a[col][col];
        for (int j = 0; j < 8; j++) a[col][j] /= d;
        for (int r = 0; r < 4; r++) {
            if (r == col) continue;
            double f = a[r][col];
            for (int j = 0; j < 8; j++) a[r][j] -= f * a[col][j];
        }
    }
    double inv[16];
    for (int i = 0; i < 4; i++)
        for (int j = 0; j < 4; j++) inv[i*4+j] = a[i][j+4];

    for (int v = 1; v < NV; v++) {
        double P[16];
        for (int i = 0; i < 4; i++)
            for (int j = 0; j < 4; j++) {
                double s = 0.0;
                for (int k = 0; k < 4; k++) s += fused[v][i*4+k] * inv[k*4+j];
                P[i*4+j] = s;
            }
        for (int i = 0; i < 3; i++)
            for (int j = 0; j < 3; j++) g_rot[v-1][i*3+j] = (float)P[i*4+j];
        for (int i = 0; i < 3; i++) g_trans[v-1][i] = (float)P[i*4+3];
    }
}

// ---------------- kernel 1: transpose features (N,C,H,W) -> (N,HW,C) --------
__global__ void k_transpose(const float* __restrict__ f) {
    __shared__ float tile[32][33];
    int n  = blockIdx.z;
    int p0 = blockIdx.x * 32;
    int tx = threadIdx.x, ty = threadIdx.y;
    tile[ty][tx] = f[((size_t)(n*CC + ty))*HWSZ + p0 + tx];
    __syncthreads();
    g_feaT[((size_t)(n*HWSZ + p0 + ty))*CC + tx] = tile[tx][ty];
}

// ---------------- kernel 2: warp + variance (planar output) -----------------
__global__ void __launch_bounds__(128) k_var(const float* __restrict__ dv) {
    __shared__ int4   s_idx[4][4][32];   // [warp][view][pt]
    __shared__ float4 s_wt [4][4][32];
    __shared__ int    s_hw [4][32];
    __shared__ float  s_var[128*33];

    const int tid  = threadIdx.x;
    const int warp = tid >> 5;
    const int lane = tid & 31;
    const int gblock = blockIdx.x * 128;

    // ---- phase 1: per-thread projection descriptors for one point ----
    {
        int g  = gblock + tid;
        int d  = g / HWSZ;
        int hw = g - d * HWSZ;
        int h  = hw / WW;
        int w  = hw - h * WW;
        float fx = (float)w, fy = (float)h;
        float depth = __ldg(dv + d);
        #pragma unroll
        for (int v = 0; v < NS; v++) {
            float r0 = g_rot[v][0], r1 = g_rot[v][1], r2 = g_rot[v][2];
            float r3 = g_rot[v][3], r4 = g_rot[v][4], r5 = g_rot[v][5];
            float r6 = g_rot[v][6], r7 = g_rot[v][7], r8 = g_rot[v][8];
            float t0 = g_trans[v][0], t1 = g_trans[v][1], t2 = g_trans[v][2];
            float rx = r0*fx + r1*fy + r2;
            float ry = r3*fx + r4*fy + r5;
            float rz = r6*fx + r7*fy + r8;
            float X = rx*depth + t0;
            float Y = ry*depth + t1;
            float Z = rz*depth + t2;
            float px = X / Z;
            float py = Y / Z;
            float x0 = floorf(px), y0 = floorf(py);
            float x1 = x0 + 1.0f,  y1 = y0 + 1.0f;
            float wx1 = px - x0, wx0 = 1.0f - wx1;
            float wy1 = py - y0, wy0 = 1.0f - wy1;
            bool vx0 = (x0 >= 0.0f) && (x0 <= (float)(WW-1));
            bool vx1 = (x1 >= 0.0f) && (x1 <= (float)(WW-1));
            bool vy0 = (y0 >= 0.0f) && (y0 <= (float)(HH-1));
            bool vy1 = (y1 >= 0.0f) && (y1 <= (float)(HH-1));
            int cx0 = (int)fminf(fmaxf(x0, 0.0f), (float)(WW-1));
            int cx1 = (int)fminf(fmaxf(x1, 0.0f), (float)(WW-1));
            int cy0 = (int)fminf(fmaxf(y0, 0.0f), (float)(HH-1));
            int cy1 = (int)fminf(fmaxf(y1, 0.0f), (float)(HH-1));
            int4 id;
            id.x = cy0*WW + cx0;  // (x0,y0)
            id.y = cy0*WW + cx1;  // (x1,y0)
            id.z = cy1*WW + cx0;  // (x0,y1)
            id.w = cy1*WW + cx1;  // (x1,y1)
            float4 wt;
            wt.x = wx0*wy0 * ((vx0 && vy0) ? 1.0f : 0.0f);
            wt.y = wx1*wy0 * ((vx1 && vy0) ? 1.0f : 0.0f);
            wt.z = wx0*wy1 * ((vx0 && vy1) ? 1.0f : 0.0f);
            wt.w = wx1*wy1 * ((vx1 && vy1) ? 1.0f : 0.0f);
            s_idx[warp][v][lane] = id;
            s_wt [warp][v][lane] = wt;
        }
        s_hw[warp][lane] = hw;
    }
    __syncwarp();

    // ---- phase 2: lanes = (cg 0..7, q 0..3); coalesced channel gathers ----
    const int cg = lane & 7;
    const int q  = lane >> 3;
    const float4* fT = (const float4*)g_feaT;  // pixel stride = 8 float4
    const float invN = 1.0f / (float)NV;

    #pragma unroll
    for (int it = 0; it < 8; it++) {
        int pt  = it*4 + q;
        int hw2 = s_hw[warp][pt];
        float4 ref = fT[hw2*8 + cg];
        float sx = ref.x, sy = ref.y, sz = ref.z, sw = ref.w;
        float qx = ref.x*ref.x, qy = ref.y*ref.y, qz = ref.z*ref.z, qw = ref.w*ref.w;
        #pragma unroll
        for (int v = 0; v < NS; v++) {
            int4   id = s_idx[warp][v][pt];
            float4 wt = s_wt [warp][v][pt];
            const float4* fv = fT + (size_t)(v+1)*HWSZ*8;
            float4 c00 = fv[id.x*8 + cg];
            float4 c01 = fv[id.y*8 + cg];
            float4 c10 = fv[id.z*8 + cg];
            float4 c11 = fv[id.w*8 + cg];
            float vx = wt.x*c00.x + wt.y*c01.x + wt.z*c10.x + wt.w*c11.x;
            float vy = wt.x*c00.y + wt.y*c01.y + wt.z*c10.y + wt.w*c11.y;
            float vz = wt.x*c00.z + wt.y*c01.z + wt.z*c10.z + wt.w*c11.z;
            float vw = wt.x*c00.w + wt.y*c01.w + wt.z*c10.w + wt.w*c11.w;
            sx += vx; sy += vy; sz += vz; sw += vw;
            qx += vx*vx; qy += vy*vy; qz += vz*vz; qw += vw*vw;
        }
        float mx = sx*invN, my = sy*invN, mz = sz*invN, mw = sw*invN;
        float vrx = qx*invN - mx*mx;
        float vry = qy*invN - my*my;
        float vrz = qz*invN - mz*mz;
        float vrw = qw*invN - mw*mw;
        int sbase = (warp*32 + pt)*33 + cg*4;
        s_var[sbase+0] = vrx;
        s_var[sbase+1] = vry;
        s_var[sbase+2] = vrz;
        s_var[sbase+3] = vrw;
    }
    __syncthreads();

    // ---- planar write: g_var[c][g] ----
    int gg = gblock + tid;
    #pragma unroll
    for (int c = 0; c < CC; c++)
        g_var[(size_t)c*DHWSZ + gg] = s_var[tid*33 + c];
}

// ---------------- kernel 3: 3x3x3 conv over 32 channels ---------------------
__global__ void __launch_bounds__(160) k_conv(const float* __restrict__ wgt) {
    const int w  = threadIdx.x;
    const int h  = blockIdx.x;
    const int d0 = blockIdx.y * 8;
    float acc[8];
    #pragma unroll
    for (int i = 0; i < 8; i++) acc[i] = 0.0f;

    for (int c = 0; c < CC; c++) {
        const float* __restrict__ vc = g_var + (size_t)c*DHWSZ;
        #pragma unroll
        for (int dy = 0; dy < 3; dy++) {
            int hy = h + dy - 1;
            if (hy < 0 || hy >= HH) continue;
            #pragma unroll
            for (int dx = 0; dx < 3; dx++) {
                int wx = w + dx - 1;
                if (wx < 0 || wx >= WW) continue;
                float k0 = __ldg(wgt + ((c*3 + 0)*3 + dy)*3 + dx);
                float k1 = __ldg(wgt + ((c*3 + 1)*3 + dy)*3 + dx);
                float k2 = __ldg(wgt + ((c*3 + 2)*3 + dy)*3 + dx);
                const float* __restrict__ base = vc + hy*WW + wx;
                #pragma unroll
                for (int dp = 0; dp < 10; dp++) {
                    int dd = d0 + dp - 1;
                    if (dd < 0 || dd >= DDEP) continue;
                    float v = __ldg(base + (size_t)dd*HWSZ);
                    if (dp <= 7)            acc[dp]   += v * k0;
                    if (dp >= 1 && dp <= 8) acc[dp-1] += v * k1;
                    if (dp >= 2)            acc[dp-2] += v * k2;
                }
            }
        }
    }
    int ob = h*WW + w;
    #pragma unroll
    for (int i = 0; i < 8; i++)
        g_cost[(size_t)(d0 + i)*HWSZ + ob] = acc[i];
}

// ---------------- kernel 4: softmax / depth / confidence --------------------
__global__ void __launch_bounds__(256) k_post(const float* __restrict__ dv,
                                              float* __restrict__ out) {
    int pix = blockIdx.x * 256 + threadIdx.x;
    float p[DDEP];
    float mx = -1e30f;
    #pragma unroll
    for (int d = 0; d < DDEP; d++) {
        p[d] = g_cost[(size_t)d*HWSZ + pix];
        mx = fmaxf(mx, p[d]);
    }
    float s = 0.0f;
    #pragma unroll
    for (int d = 0; d < DDEP; d++) { p[d] = expf(p[d] - mx); s += p[d]; }
    float inv = 1.0f / s;
    float depth = 0.0f, didx = 0.0f;
    #pragma unroll
    for (int d = 0; d < DDEP; d++) {
        float pr = p[d] * inv;
        p[d] = pr;
        depth += pr * __ldg(dv + d);
        didx  += pr * (float)d;
    }
    int di = (int)didx;
    di = min(max(di, 0), DDEP - 1);
    float conf = 0.0f;
    #pragma unroll
    for (int d = 0; d < DDEP; d++) {
        bool inwin = (d >= di - 1) && (d <= di + 2);
        conf += inwin ? p[d] : 0.0f;
    }
    out[pix]        = depth;
    out[HWSZ + pix] = conf;
}

// ---------------- launcher ---------------------------------------------------
extern "C" void kernel_launch(void* const* d_in, const int* in_sizes, int n_in,
                              void* d_out, int out_size) {
    // robust input identification by element count (all sizes distinct)
    const float* features = nullptr;  // 3,276,800
    const float* pm       = nullptr;  // 160
    const float* dv       = nullptr;  // 48
    const float* wgt      = nullptr;  // 864
    for (int i = 0; i < n_in; i++) {
        switch (in_sizes[i]) {
            case NV*CC*HWSZ: features = (const float*)d_in[i]; break;
            case 160:        pm       = (const float*)d_in[i]; break;
            case 48:         dv       = (const float*)d_in[i]; break;
            case 864:        wgt      = (const float*)d_in[i]; break;
            default: break;
        }
    }
    // fallback to positional order if anything missing
    if (!features) features = (const float*)d_in[0];
    if (!pm)       pm       = (const float*)d_in[1];
    if (!dv)       dv       = (const float*)d_in[2];
    if (!wgt)      wgt      = (const float*)d_in[3];
    float* out = (float*)d_out;

    k_setup<<<1, 32>>>(pm);
    k_transpose<<<dim3(HWSZ/32, 1, NV), dim3(32, 32)>>>(features);
    k_var<<<DHWSZ/128, 128>>>(dv);
    k_conv<<<dim3(HH, DDEP/8), 160>>>(wgt);
    k_post<<<HWSZ/256, 256>>>(dv, out);
}